// round 1
// baseline (speedup 1.0000x reference)
#include <cuda_runtime.h>
#include <cstdint>

// ---------------------------------------------------------------------------
// MTRNN cell fused as ONE block-sparse GEMM + elementwise epilogue.
//   A[B=16384, K=1344] = [input(64) | io_h(512) | fast_h(512) | slow_h(256)]
//   Wbig[K=1344, Npad=1408] (cols: out(64) | io(512) | fast(512) | slow(256) | pad(64))
//   C = A @ Wbig ; epilogue applies bias, leak, tanh, writes 4 output tensors.
// GEMM uses mma.sync.m16n8k8 TF32 (fp32 accum) for rel_err ~4e-4.
// ---------------------------------------------------------------------------

#define BATCH   16384
#define KDIM    1344
#define NPAD    1408
#define NREAL   1344

// output tensor offsets in d_out (concatenated: output, new_io, new_fast, new_slow)
#define OFF_OUT  0
#define OFF_IO   (BATCH * 64)
#define OFF_FAST (OFF_IO + BATCH * 512)
#define OFF_SLOW (OFF_FAST + BATCH * 512)

__device__ uint32_t g_Wbig[KDIM * NPAD];   // tf32 bit patterns
__device__ float    g_bias[NPAD];

__device__ __forceinline__ uint32_t f2tf32(float x) {
    uint32_t y;
    asm("cvt.rna.tf32.f32 %0, %1;" : "=r"(y) : "f"(x));
    return y;
}

__device__ __forceinline__ void mma_tf32(float* c, const uint32_t* a, const uint32_t* b) {
    asm volatile(
        "mma.sync.aligned.m16n8k8.row.col.f32.tf32.tf32.f32 "
        "{%0,%1,%2,%3}, {%4,%5,%6,%7}, {%8,%9}, {%0,%1,%2,%3};\n"
        : "+f"(c[0]), "+f"(c[1]), "+f"(c[2]), "+f"(c[3])
        : "r"(a[0]), "r"(a[1]), "r"(a[2]), "r"(a[3]), "r"(b[0]), "r"(b[1]));
}

// ---------------------------------------------------------------------------
// Prepack: scatter the 9 weight matrices into Wbig (tf32-converted), zeros
// elsewhere. Column layout: [0,64)=out, [64,576)=io, [576,1088)=fast,
// [1088,1344)=slow, [1344,1408)=pad. Row (k) layout: [0,64)=input,
// [64,576)=io_h, [576,1088)=fast_h, [1088,1344)=slow_h.
// ---------------------------------------------------------------------------
__global__ void prepack_w(
    const float* __restrict__ W_in_io,   const float* __restrict__ W_io_io,
    const float* __restrict__ W_fast_io, const float* __restrict__ W_io_fast,
    const float* __restrict__ W_fast_fast, const float* __restrict__ W_slow_fast,
    const float* __restrict__ W_fast_slow, const float* __restrict__ W_slow_slow,
    const float* __restrict__ W_io_out)
{
    int idx = blockIdx.x * blockDim.x + threadIdx.x;
    if (idx >= KDIM * NPAD) return;
    int k = idx / NPAD;
    int n = idx % NPAD;
    float v = 0.0f;
    if (n < 64) {                     // -> output cols (from io_h rows)
        if (k >= 64 && k < 576)   v = W_io_out[(k - 64) * 64 + n];
    } else if (n < 576) {             // -> io cols
        int nn = n - 64;
        if (k < 64)               v = W_in_io[k * 512 + nn];
        else if (k < 576)         v = W_io_io[(k - 64) * 512 + nn];
        else if (k < 1088)        v = W_fast_io[(k - 576) * 512 + nn];
    } else if (n < 1088) {            // -> fast cols
        int nn = n - 576;
        if (k >= 64 && k < 576)   v = W_io_fast[(k - 64) * 512 + nn];
        else if (k >= 576 && k < 1088) v = W_fast_fast[(k - 576) * 512 + nn];
        else if (k >= 1088)       v = W_slow_fast[(k - 1088) * 512 + nn];
    } else if (n < NREAL) {           // -> slow cols
        int nn = n - 1088;
        if (k >= 576 && k < 1088) v = W_fast_slow[(k - 576) * 256 + nn];
        else if (k >= 1088)       v = W_slow_slow[(k - 1088) * 256 + nn];
    }
    g_Wbig[idx] = f2tf32(v);
}

__global__ void prepack_b(
    const float* __restrict__ b_in_io,   const float* __restrict__ b_io_io,
    const float* __restrict__ b_fast_io, const float* __restrict__ b_io_fast,
    const float* __restrict__ b_fast_fast, const float* __restrict__ b_slow_fast,
    const float* __restrict__ b_fast_slow, const float* __restrict__ b_slow_slow,
    const float* __restrict__ b_io_out)
{
    int n = blockIdx.x * blockDim.x + threadIdx.x;
    if (n >= NPAD) return;
    float v = 0.0f;
    if (n < 64)        v = b_io_out[n];
    else if (n < 576)  { int nn = n - 64;   v = b_in_io[nn] + b_io_io[nn] + b_fast_io[nn]; }
    else if (n < 1088) { int nn = n - 576;  v = b_io_fast[nn] + b_fast_fast[nn] + b_slow_fast[nn]; }
    else if (n < NREAL){ int nn = n - 1088; v = b_slow_slow[nn] + b_fast_slow[nn]; }
    g_bias[n] = v;
}

// ---------------------------------------------------------------------------
// Fused GEMM + epilogue.
// CTA tile 128(M) x 128(N), BK=32, 256 threads = 8 warps as 4(M) x 2(N),
// warp tile 32x64 -> 2x8 m16n8k8 fragments.
// As: [m][36] stride-36 padding -> conflict-free frag loads (bank = 4m+k).
// Bs: [k][136] stride-136      -> conflict-free frag loads (bank = 8k+n).
// Grid (11, 128): N-tiles fastest so 11 consecutive CTAs share one 688KB
// A-stripe (L2-resident) and Wbig (7.6MB) stays in L2 -> A read from HBM once.
// ---------------------------------------------------------------------------
__global__ __launch_bounds__(256) void mtrnn_gemm(
    const float* __restrict__ inp,    const float* __restrict__ io_h,
    const float* __restrict__ fast_h, const float* __restrict__ slow_h,
    float* __restrict__ out)
{
    __shared__ uint32_t As[128 * 36];
    __shared__ uint32_t Bs[32 * 136];

    const int tid  = threadIdx.x;
    const int n0   = blockIdx.x * 128;
    const int m0   = blockIdx.y * 128;
    const int lane = tid & 31;
    const int warp = tid >> 5;
    const int wm   = warp & 3;     // 0..3 : 32-row slab
    const int wn   = warp >> 2;    // 0..1 : 64-col slab
    const int g    = lane >> 2;    // groupID 0..7
    const int tg   = lane & 3;     // thread-in-group

    float acc[2][8][4];
#pragma unroll
    for (int mt = 0; mt < 2; mt++)
#pragma unroll
        for (int nt = 0; nt < 8; nt++)
#pragma unroll
            for (int i = 0; i < 4; i++) acc[mt][nt][i] = 0.0f;

    float4 aReg[4], bReg[4];

    // ---- global load helpers (k-tile boundaries are multiples of 32, so one
    //      source tensor per tile) ----
    auto gloadA = [&](int kt) {
        int k0 = kt * 32;
        const float* src; int ld, kb;
        if (k0 < 64)        { src = inp;    ld = 64;  kb = k0; }
        else if (k0 < 576)  { src = io_h;   ld = 512; kb = k0 - 64; }
        else if (k0 < 1088) { src = fast_h; ld = 512; kb = k0 - 576; }
        else                { src = slow_h; ld = 256; kb = k0 - 1088; }
#pragma unroll
        for (int i = 0; i < 4; i++) {
            int idx = tid + i * 256;
            int r = idx >> 3, kq = idx & 7;
            aReg[i] = *(const float4*)(src + (m0 + r) * ld + kb + kq * 4);
        }
    };
    auto gloadB = [&](int kt) {
        int k0 = kt * 32;
#pragma unroll
        for (int i = 0; i < 4; i++) {
            int idx = tid + i * 256;
            int kr = idx >> 5, nq = idx & 31;
            bReg[i] = *(const float4*)((const float*)g_Wbig + (k0 + kr) * NPAD + n0 + nq * 4);
        }
    };

    gloadA(0); gloadB(0);

    for (int kt = 0; kt < KDIM / 32; kt++) {
        __syncthreads();   // previous compute done with smem
        // stage to smem (A converted to tf32; Wbig already tf32 bits)
#pragma unroll
        for (int i = 0; i < 4; i++) {
            int idx = tid + i * 256;
            int r = idx >> 3, kq = idx & 7;
            uint32_t* p = &As[r * 36 + kq * 4];
            p[0] = f2tf32(aReg[i].x); p[1] = f2tf32(aReg[i].y);
            p[2] = f2tf32(aReg[i].z); p[3] = f2tf32(aReg[i].w);
        }
#pragma unroll
        for (int i = 0; i < 4; i++) {
            int idx = tid + i * 256;
            int kr = idx >> 5, nq = idx & 31;
            *(uint4*)&Bs[kr * 136 + nq * 4] = *(uint4*)&bReg[i];
        }
        __syncthreads();

        if (kt < KDIM / 32 - 1) { gloadA(kt + 1); gloadB(kt + 1); }  // prefetch

        // ---- compute: 4 k-steps of m16n8k8 ----
#pragma unroll
        for (int kk = 0; kk < 4; kk++) {
            uint32_t afr[2][4];
#pragma unroll
            for (int mt = 0; mt < 2; mt++) {
                int r = wm * 32 + mt * 16 + g;
                int c = kk * 8 + tg;
                afr[mt][0] = As[r * 36 + c];
                afr[mt][1] = As[(r + 8) * 36 + c];
                afr[mt][2] = As[r * 36 + c + 4];
                afr[mt][3] = As[(r + 8) * 36 + c + 4];
            }
#pragma unroll
            for (int nt = 0; nt < 8; nt++) {
                uint32_t bfr[2];
                int br = kk * 8 + tg;
                int bc = wn * 64 + nt * 8 + g;
                bfr[0] = Bs[br * 136 + bc];
                bfr[1] = Bs[(br + 4) * 136 + bc];
#pragma unroll
                for (int mt = 0; mt < 2; mt++) mma_tf32(acc[mt][nt], afr[mt], bfr);
            }
        }
    }

    // ---- epilogue: bias + leak + tanh, scatter to the 4 output tensors ----
    const float C_IO   = 1.0f - 1.0f / 2.0f;     // 0.5
    const float C_FAST = 1.0f - 1.0f / 5.0f;     // 0.8
    const float C_SLOW = 1.0f - 1.0f / 70.0f;
#pragma unroll
    for (int mt = 0; mt < 2; mt++) {
#pragma unroll
        for (int nt = 0; nt < 8; nt++) {
#pragma unroll
            for (int e = 0; e < 4; e++) {
                int b  = m0 + wm * 32 + mt * 16 + g + ((e >> 1) ? 8 : 0);
                int n  = n0 + wn * 64 + nt * 8 + tg * 2 + (e & 1);
                if (n >= NREAL) continue;
                float s = acc[mt][nt][e] + g_bias[n];
                if (n < 64) {
                    out[OFF_OUT + b * 64 + n] = tanhf(s);
                } else if (n < 576) {
                    int nn = n - 64;
                    out[OFF_IO + b * 512 + nn] =
                        tanhf(C_IO * io_h[b * 512 + nn] + s * (1.0f / 2.0f));
                } else if (n < 1088) {
                    int nn = n - 576;
                    out[OFF_FAST + b * 512 + nn] =
                        tanhf(C_FAST * fast_h[b * 512 + nn] + s * (1.0f / 5.0f));
                } else {
                    int nn = n - 1088;
                    out[OFF_SLOW + b * 256 + nn] =
                        tanhf(C_SLOW * slow_h[b * 256 + nn] + s * (1.0f / 70.0f));
                }
            }
        }
    }
}

// ---------------------------------------------------------------------------
extern "C" void kernel_launch(void* const* d_in, const int* in_sizes, int n_in,
                              void* d_out, int out_size)
{
    const float* input       = (const float*)d_in[0];
    const float* io_h        = (const float*)d_in[1];
    const float* fast_h      = (const float*)d_in[2];
    const float* slow_h      = (const float*)d_in[3];
    const float* W_in_io     = (const float*)d_in[4];
    const float* b_in_io     = (const float*)d_in[5];
    const float* W_io_fast   = (const float*)d_in[6];
    const float* b_io_fast   = (const float*)d_in[7];
    const float* W_fast_fast = (const float*)d_in[8];
    const float* b_fast_fast = (const float*)d_in[9];
    const float* W_fast_slow = (const float*)d_in[10];
    const float* b_fast_slow = (const float*)d_in[11];
    const float* W_slow_slow = (const float*)d_in[12];
    const float* b_slow_slow = (const float*)d_in[13];
    const float* W_slow_fast = (const float*)d_in[14];
    const float* b_slow_fast = (const float*)d_in[15];
    const float* W_fast_io   = (const float*)d_in[16];
    const float* b_fast_io   = (const float*)d_in[17];
    const float* W_io_io     = (const float*)d_in[18];
    const float* b_io_io     = (const float*)d_in[19];
    const float* W_io_out    = (const float*)d_in[20];
    const float* b_io_out    = (const float*)d_in[21];

    prepack_w<<<(KDIM * NPAD + 255) / 256, 256>>>(
        W_in_io, W_io_io, W_fast_io, W_io_fast, W_fast_fast,
        W_slow_fast, W_fast_slow, W_slow_slow, W_io_out);
    prepack_b<<<(NPAD + 255) / 256, 256>>>(
        b_in_io, b_io_io, b_fast_io, b_io_fast, b_fast_fast,
        b_slow_fast, b_fast_slow, b_slow_slow, b_io_out);

    dim3 grid(NPAD / 128, BATCH / 128);   // N-tiles fastest for A reuse in L2
    mtrnn_gemm<<<grid, 256>>>(input, io_h, fast_h, slow_h, (float*)d_out);
}

// round 4
// speedup vs baseline: 1.3139x; 1.3139x over previous
#include <cuda_runtime.h>
#include <cstdint>

// ---------------------------------------------------------------------------
// MTRNN cell as ONE block-sparse GEMM, mma.sync.m16n8k8.tf32 (family-portable:
// no tcgen05 -- the harness PTX pass targets compute_103 family, not 103a).
//   A[16384,1344] = [input(64)|io_h(512)|fast_h(512)|slow_h(256)]  (raw f32)
//   W packed+transposed+tf32(RNA) in mma-FRAGMENT-INTERLEAVED gmem layout.
// 3-stage cp.async pipeline, CTA 128x128, BK=32, 8 warps (4Mx2N), 2 CTAs/SM.
// Epilogue: bias + leak + tanh from registers, float2 stores.
// R3 fix: fast-column region guard in w_lookup (k>=576) -- round-3 bug read
// W_fast_fast at negative indices for k<64, corrupting new_fast only.
// ---------------------------------------------------------------------------

#define BATCH 16384
#define KDIM  1344
#define NPAD  1408
#define NREAL 1344
#define NKT   42                 // K tiles of 32
#define NS    3                  // cp.async stages

#define NT8   (NPAD / 8)         // 176 n-tiles of 8
#define KT16  (KDIM / 16)        // 84 k-tiles of 16

#define OFF_OUT  0
#define OFF_IO   (BATCH * 64)
#define OFF_FAST (OFF_IO + BATCH * 512)
#define OFF_SLOW (OFF_FAST + BATCH * 512)

#define A_BYTES     18432        // 128 rows * 144B (128B data + 16B pad)
#define B_BYTES     16384        // 16 ntiles * 2 kt2 * 32 lanes * 16B
#define STAGE_BYTES (A_BYTES + B_BYTES)
#define SM_TOTAL    (NS * STAGE_BYTES)   // 104448

// B fragment layout: g_Wfrag[ntile][kt2][lane][4]
//   value[j] = W[k = kt2*16 + (lane&3) + (j&1)*4 + (j>>1)*8][n = ntile*8 + (lane>>2)]
__device__ uint32_t g_Wfrag[NT8 * KT16 * 32 * 4];    // tf32 bits
__device__ __align__(16) float g_bias[NPAD];

__device__ __forceinline__ uint32_t f2tf32(float x) {
    uint32_t y; asm("cvt.rna.tf32.f32 %0, %1;" : "=r"(y) : "f"(x)); return y;
}
__device__ __forceinline__ uint32_t smem_u32(const void* p) {
    uint32_t a;
    asm("{ .reg .u64 t; cvta.to.shared.u64 t, %1; cvt.u32.u64 %0, t; }"
        : "=r"(a) : "l"(p));
    return a;
}
__device__ __forceinline__ void cpa16(uint32_t dst, const void* src) {
    asm volatile("cp.async.cg.shared.global [%0], [%1], 16;" :: "r"(dst), "l"(src));
}
#define CP_COMMIT() asm volatile("cp.async.commit_group;" ::: "memory")
#define CP_WAIT1()  asm volatile("cp.async.wait_group 1;" ::: "memory")

__device__ __forceinline__ void mma_tf32(float* c, const uint32_t* a, const uint32_t* b) {
    asm volatile(
        "mma.sync.aligned.m16n8k8.row.col.f32.tf32.tf32.f32 "
        "{%0,%1,%2,%3}, {%4,%5,%6,%7}, {%8,%9}, {%0,%1,%2,%3};\n"
        : "+f"(c[0]), "+f"(c[1]), "+f"(c[2]), "+f"(c[3])
        : "r"(a[0]), "r"(a[1]), "r"(a[2]), "r"(a[3]), "r"(b[0]), "r"(b[1]));
}

// ---------------------------------------------------------------------------
__device__ __forceinline__ float w_lookup(
    int k, int n,
    const float* W_in_io,   const float* W_io_io,   const float* W_fast_io,
    const float* W_io_fast, const float* W_fast_fast, const float* W_slow_fast,
    const float* W_fast_slow, const float* W_slow_slow, const float* W_io_out)
{
    float v = 0.0f;
    if (n < 64) {
        if (k >= 64 && k < 576)        v = W_io_out[(k - 64) * 64 + n];
    } else if (n < 576) {
        int nn = n - 64;
        if (k < 64)                    v = W_in_io[k * 512 + nn];
        else if (k < 576)              v = W_io_io[(k - 64) * 512 + nn];
        else if (k < 1088)             v = W_fast_io[(k - 576) * 512 + nn];
    } else if (n < 1088) {
        int nn = n - 576;
        if (k >= 64 && k < 576)        v = W_io_fast[(k - 64) * 512 + nn];
        else if (k >= 576 && k < 1088) v = W_fast_fast[(k - 576) * 512 + nn];   // FIXED guard
        else if (k >= 1088)            v = W_slow_fast[(k - 1088) * 512 + nn];
    } else if (n < NREAL) {
        int nn = n - 1088;
        if (k >= 576 && k < 1088)      v = W_fast_slow[(k - 576) * 256 + nn];
        else if (k >= 1088)            v = W_slow_slow[(k - 1088) * 256 + nn];
    }
    return v;
}

__global__ void prepack_wf(
    const float* __restrict__ W_in_io,   const float* __restrict__ W_io_io,
    const float* __restrict__ W_fast_io, const float* __restrict__ W_io_fast,
    const float* __restrict__ W_fast_fast, const float* __restrict__ W_slow_fast,
    const float* __restrict__ W_fast_slow, const float* __restrict__ W_slow_slow,
    const float* __restrict__ W_io_out)
{
    int idx = blockIdx.x * blockDim.x + threadIdx.x;
    if (idx >= NT8 * KT16 * 128) return;
    int j     = idx & 3;
    int lane  = (idx >> 2) & 31;
    int t     = idx >> 7;
    int kt2   = t % KT16;
    int ntile = t / KT16;
    int n = ntile * 8 + (lane >> 2);
    int k = kt2 * 16 + (lane & 3) + (j & 1) * 4 + (j >> 1) * 8;
    float v = w_lookup(k, n, W_in_io, W_io_io, W_fast_io, W_io_fast, W_fast_fast,
                       W_slow_fast, W_fast_slow, W_slow_slow, W_io_out);
    g_Wfrag[idx] = f2tf32(v);
}

__global__ void prepack_b(
    const float* __restrict__ b_in_io,   const float* __restrict__ b_io_io,
    const float* __restrict__ b_fast_io, const float* __restrict__ b_io_fast,
    const float* __restrict__ b_fast_fast, const float* __restrict__ b_slow_fast,
    const float* __restrict__ b_fast_slow, const float* __restrict__ b_slow_slow,
    const float* __restrict__ b_io_out)
{
    int n = blockIdx.x * blockDim.x + threadIdx.x;
    if (n >= NPAD) return;
    float v = 0.0f;
    if (n < 64)        v = b_io_out[n];
    else if (n < 576)  { int nn = n - 64;   v = b_in_io[nn] + b_io_io[nn] + b_fast_io[nn]; }
    else if (n < 1088) { int nn = n - 576;  v = b_io_fast[nn] + b_fast_fast[nn] + b_slow_fast[nn]; }
    else if (n < NREAL){ int nn = n - 1088; v = b_slow_slow[nn] + b_fast_slow[nn]; }
    g_bias[n] = v;
}

// ---------------------------------------------------------------------------
__global__ __launch_bounds__(256, 2) void mtrnn_mma(
    const float* __restrict__ inp,    const float* __restrict__ io_h,
    const float* __restrict__ fast_h, const float* __restrict__ slow_h,
    float* __restrict__ out)
{
    extern __shared__ char smem[];
    const uint32_t sb = smem_u32(smem);

    const int tid  = threadIdx.x;
    const int lane = tid & 31;
    const int warp = tid >> 5;
    const int wm   = warp & 3;      // M slab 0..3 (32 rows each)
    const int wn   = warp >> 2;     // N slab 0..1 (64 cols each)
    const int g    = lane >> 2;
    const int tg   = lane & 3;

    const int n0 = blockIdx.x * 128;
    const int m0 = blockIdx.y * 128;
    const int nt8_0 = blockIdx.x * 16;

    float acc[2][8][4];
#pragma unroll
    for (int mt = 0; mt < 2; mt++)
#pragma unroll
        for (int nt = 0; nt < 8; nt++)
#pragma unroll
            for (int i = 0; i < 4; i++) acc[mt][nt][i] = 0.0f;

    // ---- stage loader: k-tile kt into stage slot s ----
    auto load_stage = [&](int kt, int s) {
        int k0 = kt * 32;
        const float* src; int ld, kb;
        if (k0 < 64)        { src = inp;    ld = 64;  kb = k0; }
        else if (k0 < 576)  { src = io_h;   ld = 512; kb = k0 - 64; }
        else if (k0 < 1088) { src = fast_h; ld = 512; kb = k0 - 576; }
        else                { src = slow_h; ld = 256; kb = k0 - 1088; }
        uint32_t aDst = sb + s * STAGE_BYTES;
        uint32_t bDst = aDst + A_BYTES;
        // A: 128 rows x 32 floats, row stride 144B in smem
#pragma unroll
        for (int i = 0; i < 4; i++) {
            int idx = tid + i * 256;
            int row = idx >> 3, seg = idx & 7;
            cpa16(aDst + row * 144 + seg * 16,
                  src + (size_t)(m0 + row) * ld + kb + seg * 4);
        }
        // B: 16 ntiles x 2 kt2 x 32 lanes x 16B, already fragment-interleaved
        const uint32_t* wsrc = g_Wfrag;
#pragma unroll
        for (int i = 0; i < 4; i++) {
            int c  = tid + i * 256;
            int ln = c >> 6, rem = c & 63;
            size_t goff = (((size_t)(nt8_0 + ln) * KT16 + (kt * 2 + (rem >> 5))) * 32
                           + (rem & 31)) * 4;
            cpa16(bDst + c * 16, wsrc + goff);
        }
    };

    // prologue: stages 0,1
    load_stage(0, 0); CP_COMMIT();
    load_stage(1, 1); CP_COMMIT();

    int s = 0;
    for (int kt = 0; kt < NKT; kt++) {
        CP_WAIT1();
        __syncthreads();

        int j = kt + 2;
        if (j < NKT) {
            int sj = s + 2; if (sj >= NS) sj -= NS;
            load_stage(j, sj);
        }
        CP_COMMIT();

        const uint32_t* As = (const uint32_t*)(smem + s * STAGE_BYTES);
        const float4*   Bs = (const float4*)(smem + s * STAGE_BYTES + A_BYTES);

#pragma unroll
        for (int kt2 = 0; kt2 < 2; kt2++) {
            float4 bf[8];
#pragma unroll
            for (int nt = 0; nt < 8; nt++)
                bf[nt] = Bs[((wn * 8 + nt) * 2 + kt2) * 32 + lane];
#pragma unroll
            for (int h = 0; h < 2; h++) {
                int kk = kt2 * 2 + h;
                uint32_t af[2][4];
#pragma unroll
                for (int mt = 0; mt < 2; mt++) {
                    int r = wm * 32 + mt * 16 + g;
                    int c = kk * 8 + tg;
                    af[mt][0] = As[r * 36 + c];
                    af[mt][1] = As[(r + 8) * 36 + c];
                    af[mt][2] = As[r * 36 + c + 4];
                    af[mt][3] = As[(r + 8) * 36 + c + 4];
                }
#pragma unroll
                for (int nt = 0; nt < 8; nt++) {
                    uint32_t bp[2];
                    if (h == 0) { bp[0] = __float_as_uint(bf[nt].x);
                                  bp[1] = __float_as_uint(bf[nt].y); }
                    else        { bp[0] = __float_as_uint(bf[nt].z);
                                  bp[1] = __float_as_uint(bf[nt].w); }
#pragma unroll
                    for (int mt = 0; mt < 2; mt++)
                        mma_tf32(acc[mt][nt], af[mt], bp);
                }
            }
        }
        if (++s == NS) s = 0;
    }

    // ---- epilogue: bias + leak + tanh, float2 stores ----
#pragma unroll
    for (int nt = 0; nt < 8; nt++) {
        int gb = n0 + wn * 64 + nt * 8;          // 8-col block, single region
        if (gb >= NREAL) continue;
        int gn = gb + tg * 2;
        float2 bi = *(const float2*)&g_bias[gn];
#pragma unroll
        for (int mt = 0; mt < 2; mt++) {
            int br = m0 + wm * 32 + mt * 16 + g;
#pragma unroll
            for (int hh = 0; hh < 2; hh++) {
                int b = br + hh * 8;
                float s0 = acc[mt][nt][hh * 2 + 0] + bi.x;
                float s1 = acc[mt][nt][hh * 2 + 1] + bi.y;
                float2 o;
                if (gb < 64) {
                    o.x = tanhf(s0); o.y = tanhf(s1);
                    *(float2*)&out[OFF_OUT + (size_t)b * 64 + gn] = o;
                } else if (gb < 576) {
                    int nn = gn - 64;
                    float2 h = *(const float2*)&io_h[(size_t)b * 512 + nn];
                    o.x = tanhf(0.5f * h.x + 0.5f * s0);
                    o.y = tanhf(0.5f * h.y + 0.5f * s1);
                    *(float2*)&out[OFF_IO + (size_t)b * 512 + nn] = o;
                } else if (gb < 1088) {
                    int nn = gn - 576;
                    float2 h = *(const float2*)&fast_h[(size_t)b * 512 + nn];
                    o.x = tanhf(0.8f * h.x + 0.2f * s0);
                    o.y = tanhf(0.8f * h.y + 0.2f * s1);
                    *(float2*)&out[OFF_FAST + (size_t)b * 512 + nn] = o;
                } else {
                    int nn = gn - 1088;
                    const float cs = 1.0f - 1.0f / 70.0f, is = 1.0f / 70.0f;
                    float2 h = *(const float2*)&slow_h[(size_t)b * 256 + nn];
                    o.x = tanhf(cs * h.x + is * s0);
                    o.y = tanhf(cs * h.y + is * s1);
                    *(float2*)&out[OFF_SLOW + (size_t)b * 256 + nn] = o;
                }
            }
        }
    }
}

// ---------------------------------------------------------------------------
extern "C" void kernel_launch(void* const* d_in, const int* in_sizes, int n_in,
                              void* d_out, int out_size)
{
    const float* input       = (const float*)d_in[0];
    const float* io_h        = (const float*)d_in[1];
    const float* fast_h      = (const float*)d_in[2];
    const float* slow_h      = (const float*)d_in[3];
    const float* W_in_io     = (const float*)d_in[4];
    const float* b_in_io     = (const float*)d_in[5];
    const float* W_io_fast   = (const float*)d_in[6];
    const float* b_io_fast   = (const float*)d_in[7];
    const float* W_fast_fast = (const float*)d_in[8];
    const float* b_fast_fast = (const float*)d_in[9];
    const float* W_fast_slow = (const float*)d_in[10];
    const float* b_fast_slow = (const float*)d_in[11];
    const float* W_slow_slow = (const float*)d_in[12];
    const float* b_slow_slow = (const float*)d_in[13];
    const float* W_slow_fast = (const float*)d_in[14];
    const float* b_slow_fast = (const float*)d_in[15];
    const float* W_fast_io   = (const float*)d_in[16];
    const float* b_fast_io   = (const float*)d_in[17];
    const float* W_io_io     = (const float*)d_in[18];
    const float* b_io_io     = (const float*)d_in[19];
    const float* W_io_out    = (const float*)d_in[20];
    const float* b_io_out    = (const float*)d_in[21];

    cudaFuncSetAttribute(mtrnn_mma, cudaFuncAttributeMaxDynamicSharedMemorySize,
                         SM_TOTAL);

    prepack_wf<<<(NT8 * KT16 * 128 + 255) / 256, 256>>>(
        W_in_io, W_io_io, W_fast_io, W_io_fast, W_fast_fast,
        W_slow_fast, W_fast_slow, W_slow_slow, W_io_out);
    prepack_b<<<(NPAD + 255) / 256, 256>>>(
        b_in_io, b_io_io, b_fast_io, b_io_fast, b_fast_fast,
        b_slow_fast, b_fast_slow, b_slow_slow, b_io_out);

    dim3 grid(NPAD / 128, BATCH / 128);   // N fastest: A stripe reused in L2
    mtrnn_mma<<<grid, 256, SM_TOTAL>>>(input, io_h, fast_h, slow_h, (float*)d_out);
}

// round 5
// speedup vs baseline: 2.0851x; 1.5869x over previous
#include <cuda_runtime.h>
#include <cuda_fp16.h>
#include <cstdint>

// ---------------------------------------------------------------------------
// MTRNN cell as ONE block-sparse fp16 GEMM (mma.sync.m16n8k16.f32.f16.f16.f32;
// legacy path -- harness targets compute_103 family so tcgen05 is unavailable).
//   Pre-pass: A[16384,1344] = [input|io_h|fast_h|slow_h] converted f32->fp16
//   into g_Ah with a per-16-k fragment permutation so A-frag loads are LDS.64.
//   W packed+transposed+fp16 in exact m16n8k16 B-fragment order (g_WfragH).
// Main: CTA 128x128, BK=64, 21 k-tiles, 3-stage cp.async, 8 warps (4Mx2N),
// 2 CTAs/SM. Epilogue: bias + leak + tanh from registers, float2 stores.
// fp16 has the same 10-bit mantissa as tf32 (rel_err ~4e-4) at 2x the rate.
// ---------------------------------------------------------------------------

#define BATCH 16384
#define KDIM  1344
#define NPAD  1408
#define NREAL 1344
#define NKT   21                 // K tiles of 64
#define NS    3                  // cp.async stages

#define NT8   (NPAD / 8)         // 176 n-tiles of 8
#define KT32  (KDIM / 32)        // 42

#define OFF_OUT  0
#define OFF_IO   (BATCH * 64)
#define OFF_FAST (OFF_IO + BATCH * 512)
#define OFF_SLOW (OFF_FAST + BATCH * 512)

// smem stage: A 128 rows * 160B (128B data + 32B pad; stride%128B-bank magic:
// 20 doubles ≡ 4 mod 16 -> LDS.64 frag loads conflict-free) + B 16KB
#define A_STRIDE_B  160
#define A_BYTES     (128 * A_STRIDE_B)      // 20480
#define B_BYTES     16384                   // 16 nt * 2 kt32 * 32 lanes * 16B
#define STAGE_BYTES (A_BYTES + B_BYTES)     // 36864
#define SM_TOTAL    (NS * STAGE_BYTES)      // 110592

// prep kernel block partition
#define ABLKS 21504     // 16384*1344/4 halves-per-thread(4) /256
#define WBLKS 3696      // 1408*1344/2 u32 /256
#define BBLKS 6

// A: fp16, row-major 1344/row, per-16k block physically ordered
//    [2tg,2tg+1,2tg+8,2tg+9] at half-offset 4*tg  (tg=0..3)
__device__ __half g_Ah[(size_t)BATCH * KDIM];
// B: [ntile][kt32][lane][4 x u32]  u32 u = kkLocal*2+reg;
//    reg0 = halves W[kb+2tg],W[kb+2tg+1]; reg1 = W[kb+2tg+8],W[kb+2tg+9]
__device__ uint32_t g_WfragH[(size_t)NT8 * KT32 * 32 * 4];
__device__ __align__(16) float g_bias[NPAD];

__device__ __forceinline__ uint32_t smem_u32(const void* p) {
    uint32_t a;
    asm("{ .reg .u64 t; cvta.to.shared.u64 t, %1; cvt.u32.u64 %0, t; }"
        : "=r"(a) : "l"(p));
    return a;
}
__device__ __forceinline__ void cpa16(uint32_t dst, const void* src) {
    asm volatile("cp.async.cg.shared.global [%0], [%1], 16;" :: "r"(dst), "l"(src));
}
#define CP_COMMIT() asm volatile("cp.async.commit_group;" ::: "memory")
#define CP_WAIT1()  asm volatile("cp.async.wait_group 1;" ::: "memory")

__device__ __forceinline__ void mma_f16(float* c, uint32_t a0, uint32_t a1,
                                        uint32_t a2, uint32_t a3,
                                        uint32_t b0, uint32_t b1) {
    asm volatile(
        "mma.sync.aligned.m16n8k16.row.col.f32.f16.f16.f32 "
        "{%0,%1,%2,%3}, {%4,%5,%6,%7}, {%8,%9}, {%0,%1,%2,%3};\n"
        : "+f"(c[0]), "+f"(c[1]), "+f"(c[2]), "+f"(c[3])
        : "r"(a0), "r"(a1), "r"(a2), "r"(a3), "r"(b0), "r"(b1));
}

// ---------------------------------------------------------------------------
__device__ __forceinline__ float w_lookup(
    int k, int n,
    const float* W_in_io,   const float* W_io_io,   const float* W_fast_io,
    const float* W_io_fast, const float* W_fast_fast, const float* W_slow_fast,
    const float* W_fast_slow, const float* W_slow_slow, const float* W_io_out)
{
    float v = 0.0f;
    if (n < 64) {
        if (k >= 64 && k < 576)        v = W_io_out[(k - 64) * 64 + n];
    } else if (n < 576) {
        int nn = n - 64;
        if (k < 64)                    v = W_in_io[k * 512 + nn];
        else if (k < 576)              v = W_io_io[(k - 64) * 512 + nn];
        else if (k < 1088)             v = W_fast_io[(k - 576) * 512 + nn];
    } else if (n < 1088) {
        int nn = n - 576;
        if (k >= 64 && k < 576)        v = W_io_fast[(k - 64) * 512 + nn];
        else if (k >= 576 && k < 1088) v = W_fast_fast[(k - 576) * 512 + nn];
        else if (k >= 1088)            v = W_slow_fast[(k - 1088) * 512 + nn];
    } else if (n < NREAL) {
        int nn = n - 1088;
        if (k >= 576 && k < 1088)      v = W_fast_slow[(k - 576) * 256 + nn];
        else if (k >= 1088)            v = W_slow_slow[(k - 1088) * 256 + nn];
    }
    return v;
}

// One prep kernel (keeps launch count at 2/call): A-convert | W-pack | bias
__global__ void prep(
    const float* __restrict__ inp,    const float* __restrict__ io_h,
    const float* __restrict__ fast_h, const float* __restrict__ slow_h,
    const float* __restrict__ W_in_io,   const float* __restrict__ W_io_io,
    const float* __restrict__ W_fast_io, const float* __restrict__ W_io_fast,
    const float* __restrict__ W_fast_fast, const float* __restrict__ W_slow_fast,
    const float* __restrict__ W_fast_slow, const float* __restrict__ W_slow_slow,
    const float* __restrict__ W_io_out,
    const float* __restrict__ b_in_io,   const float* __restrict__ b_io_io,
    const float* __restrict__ b_fast_io, const float* __restrict__ b_io_fast,
    const float* __restrict__ b_fast_fast, const float* __restrict__ b_slow_fast,
    const float* __restrict__ b_fast_slow, const float* __restrict__ b_slow_slow,
    const float* __restrict__ b_io_out)
{
    int bid = blockIdx.x;
    if (bid < ABLKS) {
        // ---- A convert: one thread = 4 output halves (8B store) ----
        int idx = bid * 256 + threadIdx.x;
        int row = idx / 336;              // 336 quad-groups per row
        int o   = (idx % 336) * 4;        // half offset within row
        int blk = o >> 4;                 // 16-k block
        int tg  = (o & 15) >> 2;
        int k0  = blk * 16 + 2 * tg;      // logical k of first pair
        const float* src; int ld, kb;
        if (k0 < 64)        { src = inp;    ld = 64;  kb = k0; }
        else if (k0 < 576)  { src = io_h;   ld = 512; kb = k0 - 64; }
        else if (k0 < 1088) { src = fast_h; ld = 512; kb = k0 - 576; }
        else                { src = slow_h; ld = 256; kb = k0 - 1088; }
        float2 p0 = *(const float2*)(src + (size_t)row * ld + kb);
        float2 p1 = *(const float2*)(src + (size_t)row * ld + kb + 8);
        __half2* dst = (__half2*)(g_Ah + (size_t)row * KDIM + o);
        dst[0] = __floats2half2_rn(p0.x, p0.y);
        dst[1] = __floats2half2_rn(p1.x, p1.y);
    } else if (bid < ABLKS + WBLKS) {
        // ---- W pack: one thread = one u32 (2 halves) in frag order ----
        int idx  = (bid - ABLKS) * 256 + threadIdx.x;
        int u    = idx & 3;
        int lane = (idx >> 2) & 31;
        int t    = idx >> 7;
        int kt32 = t % KT32;
        int nt   = t / KT32;
        int n    = nt * 8 + (lane >> 2);
        int tg   = lane & 3;
        int kb   = kt32 * 32 + (u >> 1) * 16;
        int k    = kb + 2 * tg + (u & 1) * 8;
        float lo = w_lookup(k, n, W_in_io, W_io_io, W_fast_io, W_io_fast,
                            W_fast_fast, W_slow_fast, W_fast_slow, W_slow_slow,
                            W_io_out);
        float hi = w_lookup(k + 1, n, W_in_io, W_io_io, W_fast_io, W_io_fast,
                            W_fast_fast, W_slow_fast, W_fast_slow, W_slow_slow,
                            W_io_out);
        __half2 h = __floats2half2_rn(lo, hi);
        g_WfragH[idx] = *(uint32_t*)&h;
    } else {
        // ---- bias ----
        int n = (bid - ABLKS - WBLKS) * 256 + threadIdx.x;
        if (n >= NPAD) return;
        float v = 0.0f;
        if (n < 64)        v = b_io_out[n];
        else if (n < 576)  { int nn = n - 64;   v = b_in_io[nn] + b_io_io[nn] + b_fast_io[nn]; }
        else if (n < 1088) { int nn = n - 576;  v = b_io_fast[nn] + b_fast_fast[nn] + b_slow_fast[nn]; }
        else if (n < NREAL){ int nn = n - 1088; v = b_slow_slow[nn] + b_fast_slow[nn]; }
        g_bias[n] = v;
    }
}

// ---------------------------------------------------------------------------
__global__ __launch_bounds__(256, 2) void mtrnn_mma(
    const float* __restrict__ io_h, const float* __restrict__ fast_h,
    const float* __restrict__ slow_h, float* __restrict__ out)
{
    extern __shared__ char smem[];
    const uint32_t sb = smem_u32(smem);

    const int tid  = threadIdx.x;
    const int lane = tid & 31;
    const int warp = tid >> 5;
    const int wm   = warp & 3;      // M slab 0..3 (32 rows each)
    const int wn   = warp >> 2;     // N slab 0..1 (64 cols each)
    const int g    = lane >> 2;
    const int tg   = lane & 3;

    const int n0 = blockIdx.x * 128;
    const int m0 = blockIdx.y * 128;
    const int nt8_0 = blockIdx.x * 16;

    float acc[2][8][4];
#pragma unroll
    for (int mt = 0; mt < 2; mt++)
#pragma unroll
        for (int nt = 0; nt < 8; nt++)
#pragma unroll
            for (int i = 0; i < 4; i++) acc[mt][nt][i] = 0.0f;

    // ---- stage loader: k-tile kt (64 halves) into stage slot s ----
    auto load_stage = [&](int kt, int s) {
        uint32_t aDst = sb + s * STAGE_BYTES;
        uint32_t bDst = aDst + A_BYTES;
        const __half* asrc = g_Ah + (size_t)m0 * KDIM + kt * 64;
        // A: 128 rows x 64 halves (128B), smem row stride 160B
#pragma unroll
        for (int i = 0; i < 4; i++) {
            int idx = tid + i * 256;
            int row = idx >> 3, seg = idx & 7;
            cpa16(aDst + row * A_STRIDE_B + seg * 16,
                  asrc + (size_t)row * KDIM + seg * 8);
        }
        // B: [16 nt][2 kt32-half][32 lanes] x 16B, already fragment-interleaved
#pragma unroll
        for (int i = 0; i < 4; i++) {
            int c  = tid + i * 256;
            int nt = c >> 6, rem = c & 63;
            size_t goff = ((((size_t)(nt8_0 + nt) * KT32 + (kt * 2 + (rem >> 5))) * 32
                            + (rem & 31)) * 4);
            cpa16(bDst + c * 16, g_WfragH + goff);
        }
    };

    load_stage(0, 0); CP_COMMIT();
    load_stage(1, 1); CP_COMMIT();

    int s = 0;
    for (int kt = 0; kt < NKT; kt++) {
        CP_WAIT1();
        __syncthreads();

        int j = kt + 2;
        if (j < NKT) {
            int sj = s + 2; if (sj >= NS) sj -= NS;
            load_stage(j, sj);
        }
        CP_COMMIT();

        const uint2*  As2 = (const uint2*)(smem + s * STAGE_BYTES);   // 8B units
        const float4* Bs4 = (const float4*)(smem + s * STAGE_BYTES + A_BYTES);

#pragma unroll
        for (int kt2 = 0; kt2 < 2; kt2++) {        // 32-k halves of the tile
            float4 bf[8];
#pragma unroll
            for (int nt = 0; nt < 8; nt++)
                bf[nt] = Bs4[((wn * 8 + nt) * 2 + kt2) * 32 + lane];
#pragma unroll
            for (int kk = 0; kk < 2; kk++) {       // 16-k mma steps
                uint2 alo[2], ahi[2];
#pragma unroll
                for (int mt = 0; mt < 2; mt++) {
                    int r = wm * 32 + mt * 16 + g;
                    int o = r * 20 + kt2 * 8 + kk * 4 + tg;     // in 8B units
                    alo[mt] = As2[o];
                    ahi[mt] = As2[o + 8 * 20];                  // row + 8
                }
#pragma unroll
                for (int nt = 0; nt < 8; nt++) {
                    uint32_t b0, b1;
                    if (kk == 0) { b0 = __float_as_uint(bf[nt].x);
                                   b1 = __float_as_uint(bf[nt].y); }
                    else         { b0 = __float_as_uint(bf[nt].z);
                                   b1 = __float_as_uint(bf[nt].w); }
#pragma unroll
                    for (int mt = 0; mt < 2; mt++)
                        mma_f16(acc[mt][nt], alo[mt].x, ahi[mt].x,
                                alo[mt].y, ahi[mt].y, b0, b1);
                }
            }
        }
        if (++s == NS) s = 0;
    }

    // ---- epilogue: bias + leak + tanh, float2 stores ----
#pragma unroll
    for (int nt = 0; nt < 8; nt++) {
        int gb = n0 + wn * 64 + nt * 8;
        if (gb >= NREAL) continue;
        int gn = gb + tg * 2;
        float2 bi = *(const float2*)&g_bias[gn];
#pragma unroll
        for (int mt = 0; mt < 2; mt++) {
            int br = m0 + wm * 32 + mt * 16 + g;
#pragma unroll
            for (int hh = 0; hh < 2; hh++) {
                int b = br + hh * 8;
                float s0 = acc[mt][nt][hh * 2 + 0] + bi.x;
                float s1 = acc[mt][nt][hh * 2 + 1] + bi.y;
                float2 o;
                if (gb < 64) {
                    o.x = tanhf(s0); o.y = tanhf(s1);
                    *(float2*)&out[OFF_OUT + (size_t)b * 64 + gn] = o;
                } else if (gb < 576) {
                    int nn = gn - 64;
                    float2 h = *(const float2*)&io_h[(size_t)b * 512 + nn];
                    o.x = tanhf(0.5f * h.x + 0.5f * s0);
                    o.y = tanhf(0.5f * h.y + 0.5f * s1);
                    *(float2*)&out[OFF_IO + (size_t)b * 512 + nn] = o;
                } else if (gb < 1088) {
                    int nn = gn - 576;
                    float2 h = *(const float2*)&fast_h[(size_t)b * 512 + nn];
                    o.x = tanhf(0.8f * h.x + 0.2f * s0);
                    o.y = tanhf(0.8f * h.y + 0.2f * s1);
                    *(float2*)&out[OFF_FAST + (size_t)b * 512 + nn] = o;
                } else {
                    int nn = gn - 1088;
                    const float cs = 1.0f - 1.0f / 70.0f, is = 1.0f / 70.0f;
                    float2 h = *(const float2*)&slow_h[(size_t)b * 256 + nn];
                    o.x = tanhf(cs * h.x + is * s0);
                    o.y = tanhf(cs * h.y + is * s1);
                    *(float2*)&out[OFF_SLOW + (size_t)b * 256 + nn] = o;
                }
            }
        }
    }
}

// ---------------------------------------------------------------------------
extern "C" void kernel_launch(void* const* d_in, const int* in_sizes, int n_in,
                              void* d_out, int out_size)
{
    const float* input       = (const float*)d_in[0];
    const float* io_h        = (const float*)d_in[1];
    const float* fast_h      = (const float*)d_in[2];
    const float* slow_h      = (const float*)d_in[3];
    const float* W_in_io     = (const float*)d_in[4];
    const float* b_in_io     = (const float*)d_in[5];
    const float* W_io_fast   = (const float*)d_in[6];
    const float* b_io_fast   = (const float*)d_in[7];
    const float* W_fast_fast = (const float*)d_in[8];
    const float* b_fast_fast = (const float*)d_in[9];
    const float* W_fast_slow = (const float*)d_in[10];
    const float* b_fast_slow = (const float*)d_in[11];
    const float* W_slow_slow = (const float*)d_in[12];
    const float* b_slow_slow = (const float*)d_in[13];
    const float* W_slow_fast = (const float*)d_in[14];
    const float* b_slow_fast = (const float*)d_in[15];
    const float* W_fast_io   = (const float*)d_in[16];
    const float* b_fast_io   = (const float*)d_in[17];
    const float* W_io_io     = (const float*)d_in[18];
    const float* b_io_io     = (const float*)d_in[19];
    const float* W_io_out    = (const float*)d_in[20];
    const float* b_io_out    = (const float*)d_in[21];

    cudaFuncSetAttribute(mtrnn_mma, cudaFuncAttributeMaxDynamicSharedMemorySize,
                         SM_TOTAL);

    prep<<<ABLKS + WBLKS + BBLKS, 256>>>(
        input, io_h, fast_h, slow_h,
        W_in_io, W_io_io, W_fast_io, W_io_fast, W_fast_fast,
        W_slow_fast, W_fast_slow, W_slow_slow, W_io_out,
        b_in_io, b_io_io, b_fast_io, b_io_fast, b_fast_fast,
        b_slow_fast, b_fast_slow, b_slow_slow, b_io_out);

    dim3 grid(NPAD / 128, BATCH / 128);   // N fastest: A stripe reused in L2
    mtrnn_mma<<<grid, 256, SM_TOTAL>>>(io_h, fast_h, slow_h, (float*)d_out);
}

// round 6
// speedup vs baseline: 2.2760x; 1.0916x over previous
#include <cuda_runtime.h>
#include <cuda_fp16.h>
#include <cstdint>

// ---------------------------------------------------------------------------
// MTRNN cell as ONE block-sparse fp16 GEMM (mma.sync.m16n8k16, legacy path --
// harness targets compute_103 family so tcgen05 is unavailable).
// R6: (1) exact k-tile skipping per n-block (packed W is 76% dense and the
//     zero blocks are k-range aligned: 193/231 tiles, -16.5% work, bit-exact);
//     (2) ALU diet: 32-bit gmem offsets advanced by constant strides,
//     mainloop unrolled by 3 so stage slots (and all smem addressing) are
//     compile-time. R5 ncu: tensor 40.9% / alu 41.1% -> issue-slot theft.
// ---------------------------------------------------------------------------

#define BATCH 16384
#define KDIM  1344
#define NPAD  1408
#define NREAL 1344
#define NS    3

#define NT8   (NPAD / 8)         // 176
#define KT32  (KDIM / 32)        // 42

#define OFF_OUT  0
#define OFF_IO   (BATCH * 64)
#define OFF_FAST (OFF_IO + BATCH * 512)
#define OFF_SLOW (OFF_FAST + BATCH * 512)

#define A_STRIDE_B  160
#define A_BYTES     (128 * A_STRIDE_B)      // 20480
#define B_BYTES     16384
#define STAGE_BYTES (A_BYTES + B_BYTES)     // 36864
#define SM_TOTAL    (NS * STAGE_BYTES)      // 110592

#define ABLKS 21504
#define WBLKS 3696
#define BBLKS 6

__device__ __half g_Ah[(size_t)BATCH * KDIM];
__device__ uint32_t g_WfragH[(size_t)NT8 * KT32 * 32 * 4];
__device__ __align__(16) float g_bias[NPAD];

__device__ __forceinline__ uint32_t smem_u32(const void* p) {
    uint32_t a;
    asm("{ .reg .u64 t; cvta.to.shared.u64 t, %1; cvt.u32.u64 %0, t; }"
        : "=r"(a) : "l"(p));
    return a;
}
__device__ __forceinline__ void cpa16(uint32_t dst, const void* src) {
    asm volatile("cp.async.cg.shared.global [%0], [%1], 16;" :: "r"(dst), "l"(src));
}
#define CP_COMMIT() asm volatile("cp.async.commit_group;" ::: "memory")
#define CP_WAIT1()  asm volatile("cp.async.wait_group 1;" ::: "memory")

__device__ __forceinline__ void mma_f16(float* c, uint32_t a0, uint32_t a1,
                                        uint32_t a2, uint32_t a3,
                                        uint32_t b0, uint32_t b1) {
    asm volatile(
        "mma.sync.aligned.m16n8k16.row.col.f32.f16.f16.f32 "
        "{%0,%1,%2,%3}, {%4,%5,%6,%7}, {%8,%9}, {%0,%1,%2,%3};\n"
        : "+f"(c[0]), "+f"(c[1]), "+f"(c[2]), "+f"(c[3])
        : "r"(a0), "r"(a1), "r"(a2), "r"(a3), "r"(b0), "r"(b1));
}

// ---------------------------------------------------------------------------
__device__ __forceinline__ float w_lookup(
    int k, int n,
    const float* W_in_io,   const float* W_io_io,   const float* W_fast_io,
    const float* W_io_fast, const float* W_fast_fast, const float* W_slow_fast,
    const float* W_fast_slow, const float* W_slow_slow, const float* W_io_out)
{
    float v = 0.0f;
    if (n < 64) {
        if (k >= 64 && k < 576)        v = W_io_out[(k - 64) * 64 + n];
    } else if (n < 576) {
        int nn = n - 64;
        if (k < 64)                    v = W_in_io[k * 512 + nn];
        else if (k < 576)              v = W_io_io[(k - 64) * 512 + nn];
        else if (k < 1088)             v = W_fast_io[(k - 576) * 512 + nn];
    } else if (n < 1088) {
        int nn = n - 576;
        if (k >= 64 && k < 576)        v = W_io_fast[(k - 64) * 512 + nn];
        else if (k >= 576 && k < 1088) v = W_fast_fast[(k - 576) * 512 + nn];
        else if (k >= 1088)            v = W_slow_fast[(k - 1088) * 512 + nn];
    } else if (n < NREAL) {
        int nn = n - 1088;
        if (k >= 576 && k < 1088)      v = W_fast_slow[(k - 576) * 256 + nn];
        else if (k >= 1088)            v = W_slow_slow[(k - 1088) * 256 + nn];
    }
    return v;
}

__global__ void prep(
    const float* __restrict__ inp,    const float* __restrict__ io_h,
    const float* __restrict__ fast_h, const float* __restrict__ slow_h,
    const float* __restrict__ W_in_io,   const float* __restrict__ W_io_io,
    const float* __restrict__ W_fast_io, const float* __restrict__ W_io_fast,
    const float* __restrict__ W_fast_fast, const float* __restrict__ W_slow_fast,
    const float* __restrict__ W_fast_slow, const float* __restrict__ W_slow_slow,
    const float* __restrict__ W_io_out,
    const float* __restrict__ b_in_io,   const float* __restrict__ b_io_io,
    const float* __restrict__ b_fast_io, const float* __restrict__ b_io_fast,
    const float* __restrict__ b_fast_fast, const float* __restrict__ b_slow_fast,
    const float* __restrict__ b_fast_slow, const float* __restrict__ b_slow_slow,
    const float* __restrict__ b_io_out)
{
    int bid = blockIdx.x;
    if (bid < ABLKS) {
        int idx = bid * 256 + threadIdx.x;
        int row = idx / 336;
        int o   = (idx % 336) * 4;
        int blk = o >> 4;
        int tg  = (o & 15) >> 2;
        int k0  = blk * 16 + 2 * tg;
        const float* src; int ld, kb;
        if (k0 < 64)        { src = inp;    ld = 64;  kb = k0; }
        else if (k0 < 576)  { src = io_h;   ld = 512; kb = k0 - 64; }
        else if (k0 < 1088) { src = fast_h; ld = 512; kb = k0 - 576; }
        else                { src = slow_h; ld = 256; kb = k0 - 1088; }
        float2 p0 = *(const float2*)(src + (size_t)row * ld + kb);
        float2 p1 = *(const float2*)(src + (size_t)row * ld + kb + 8);
        __half2* dst = (__half2*)(g_Ah + (size_t)row * KDIM + o);
        dst[0] = __floats2half2_rn(p0.x, p0.y);
        dst[1] = __floats2half2_rn(p1.x, p1.y);
    } else if (bid < ABLKS + WBLKS) {
        int idx  = (bid - ABLKS) * 256 + threadIdx.x;
        int u    = idx & 3;
        int lane = (idx >> 2) & 31;
        int t    = idx >> 7;
        int kt32 = t % KT32;
        int nt   = t / KT32;
        int n    = nt * 8 + (lane >> 2);
        int tg   = lane & 3;
        int kb   = kt32 * 32 + (u >> 1) * 16;
        int k    = kb + 2 * tg + (u & 1) * 8;
        float lo = w_lookup(k, n, W_in_io, W_io_io, W_fast_io, W_io_fast,
                            W_fast_fast, W_slow_fast, W_fast_slow, W_slow_slow,
                            W_io_out);
        float hi = w_lookup(k + 1, n, W_in_io, W_io_io, W_fast_io, W_io_fast,
                            W_fast_fast, W_slow_fast, W_fast_slow, W_slow_slow,
                            W_io_out);
        __half2 h = __floats2half2_rn(lo, hi);
        g_WfragH[idx] = *(uint32_t*)&h;
    } else {
        int n = (bid - ABLKS - WBLKS) * 256 + threadIdx.x;
        if (n >= NPAD) return;
        float v = 0.0f;
        if (n < 64)        v = b_io_out[n];
        else if (n < 576)  { int nn = n - 64;   v = b_in_io[nn] + b_io_io[nn] + b_fast_io[nn]; }
        else if (n < 1088) { int nn = n - 576;  v = b_io_fast[nn] + b_fast_fast[nn] + b_slow_fast[nn]; }
        else if (n < NREAL){ int nn = n - 1088; v = b_slow_slow[nn] + b_fast_slow[nn]; }
        g_bias[n] = v;
    }
}

// ---------------------------------------------------------------------------
__global__ __launch_bounds__(256, 2) void mtrnn_mma(
    const float* __restrict__ io_h, const float* __restrict__ fast_h,
    const float* __restrict__ slow_h, float* __restrict__ out)
{
    extern __shared__ char smem[];
    const uint32_t sb = smem_u32(smem);

    const int tid  = threadIdx.x;
    const int lane = tid & 31;
    const int warp = tid >> 5;
    const int wm   = warp & 3;
    const int wn   = warp >> 2;
    const int g    = lane >> 2;
    const int tg   = lane & 3;

    const int n0 = blockIdx.x * 128;
    const int m0 = blockIdx.y * 128;
    const int nt8_0 = blockIdx.x * 16;

    // ---- exact k-range for this n-block (packed W block sparsity) ----
    int nhi = n0 + 128; if (nhi > NREAL) nhi = NREAL;
    int klo = KDIM, khi = 0;
    if (n0 < 64)                 { if (64 < klo) klo = 64;  if (576 > khi) khi = 576; }
    if (n0 < 576 && nhi > 64)    { klo = 0;                 if (1088 > khi) khi = 1088; }
    if (n0 < 1088 && nhi > 576)  { if (64 < klo) klo = 64;  khi = KDIM; }
    if (nhi > 1088)              { if (576 < klo) klo = 576; khi = KDIM; }
    const int kt_lo = klo >> 6;
    const int nkt   = ((khi + 63) >> 6) - kt_lo;    // 12..21

    float acc[2][8][4];
#pragma unroll
    for (int mt = 0; mt < 2; mt++)
#pragma unroll
        for (int nt = 0; nt < 8; nt++)
#pragma unroll
            for (int i = 0; i < 4; i++) acc[mt][nt][i] = 0.0f;

    // ---- per-thread load descriptors: 32-bit byte offsets, constant strides
    const char* aBase = (const char*)g_Ah;
    const char* bBase = (const char*)g_WfragH;
    uint32_t aSm[4], aGo[4], bSm[4], bGo[4];
#pragma unroll
    for (int i = 0; i < 4; i++) {
        int idx = tid + i * 256;
        int row = idx >> 3, seg = idx & 7;
        aSm[i] = (uint32_t)(row * A_STRIDE_B + seg * 16);
        aGo[i] = ((uint32_t)(m0 + row) * KDIM + (uint32_t)kt_lo * 64 + seg * 8) * 2;
        int nt = idx >> 6, rem = idx & 63;
        bSm[i] = (uint32_t)(A_BYTES + idx * 16);
        bGo[i] = (((uint32_t)(nt8_0 + nt) * KT32 + (uint32_t)kt_lo * 2 + (rem >> 5)) * 32
                  + (rem & 31)) * 16;
    }

    auto load_slot = [&](int slot) {                  // called with literals
        uint32_t aD = sb + slot * STAGE_BYTES;
#pragma unroll
        for (int i = 0; i < 4; i++) cpa16(aD + aSm[i], aBase + aGo[i]);
#pragma unroll
        for (int i = 0; i < 4; i++) cpa16(aD + bSm[i], bBase + bGo[i]);
#pragma unroll
        for (int i = 0; i < 4; i++) { aGo[i] += 128; bGo[i] += 1024; }
    };

    auto compute_slot = [&](int slot) {
        const uint2*  As2 = (const uint2*)(smem + slot * STAGE_BYTES);
        const float4* Bs4 = (const float4*)(smem + slot * STAGE_BYTES + A_BYTES);
#pragma unroll
        for (int kt2 = 0; kt2 < 2; kt2++) {
            float4 bf[8];
#pragma unroll
            for (int nt = 0; nt < 8; nt++)
                bf[nt] = Bs4[((wn * 8 + nt) * 2 + kt2) * 32 + lane];
#pragma unroll
            for (int kk = 0; kk < 2; kk++) {
                uint2 alo[2], ahi[2];
#pragma unroll
                for (int mt = 0; mt < 2; mt++) {
                    int r = wm * 32 + mt * 16 + g;
                    int o = r * 20 + kt2 * 8 + kk * 4 + tg;
                    alo[mt] = As2[o];
                    ahi[mt] = As2[o + 8 * 20];
                }
#pragma unroll
                for (int nt = 0; nt < 8; nt++) {
                    uint32_t b0, b1;
                    if (kk == 0) { b0 = __float_as_uint(bf[nt].x);
                                   b1 = __float_as_uint(bf[nt].y); }
                    else         { b0 = __float_as_uint(bf[nt].z);
                                   b1 = __float_as_uint(bf[nt].w); }
#pragma unroll
                    for (int mt = 0; mt < 2; mt++)
                        mma_f16(acc[mt][nt], alo[mt].x, ahi[mt].x,
                                alo[mt].y, ahi[mt].y, b0, b1);
                }
            }
        }
    };

    // ---- pipelined mainloop, unrolled by 3 so stage slots are literal ----
    load_slot(0); CP_COMMIT();
    load_slot(1); CP_COMMIT();
    int ld = 2;

#define STEP(J) do {                                   \
        CP_WAIT1(); __syncthreads();                   \
        if (ld < nkt) load_slot(((J) + 2) % 3);        \
        CP_COMMIT();                                   \
        compute_slot(J);                               \
        ld++;                                          \
    } while (0)

    int it = 0;
    while (it + 3 <= nkt) { STEP(0); STEP(1); STEP(2); it += 3; }
    if (it < nkt) { STEP(0); it++; }
    if (it < nkt) { STEP(1); it++; }
#undef STEP

    // ---- epilogue: bias + leak + tanh, float2 stores ----
#pragma unroll
    for (int nt = 0; nt < 8; nt++) {
        int gb = n0 + wn * 64 + nt * 8;
        if (gb >= NREAL) continue;
        int gn = gb + tg * 2;
        float2 bi = *(const float2*)&g_bias[gn];
#pragma unroll
        for (int mt = 0; mt < 2; mt++) {
            int br = m0 + wm * 32 + mt * 16 + g;
#pragma unroll
            for (int hh = 0; hh < 2; hh++) {
                int b = br + hh * 8;
                float s0 = acc[mt][nt][hh * 2 + 0] + bi.x;
                float s1 = acc[mt][nt][hh * 2 + 1] + bi.y;
                float2 o;
                if (gb < 64) {
                    o.x = tanhf(s0); o.y = tanhf(s1);
                    *(float2*)&out[OFF_OUT + (size_t)b * 64 + gn] = o;
                } else if (gb < 576) {
                    int nn = gn - 64;
                    float2 h = *(const float2*)&io_h[(size_t)b * 512 + nn];
                    o.x = tanhf(0.5f * h.x + 0.5f * s0);
                    o.y = tanhf(0.5f * h.y + 0.5f * s1);
                    *(float2*)&out[OFF_IO + (size_t)b * 512 + nn] = o;
                } else if (gb < 1088) {
                    int nn = gn - 576;
                    float2 h = *(const float2*)&fast_h[(size_t)b * 512 + nn];
                    o.x = tanhf(0.8f * h.x + 0.2f * s0);
                    o.y = tanhf(0.8f * h.y + 0.2f * s1);
                    *(float2*)&out[OFF_FAST + (size_t)b * 512 + nn] = o;
                } else {
                    int nn = gn - 1088;
                    const float cs = 1.0f - 1.0f / 70.0f, is = 1.0f / 70.0f;
                    float2 h = *(const float2*)&slow_h[(size_t)b * 256 + nn];
                    o.x = tanhf(cs * h.x + is * s0);
                    o.y = tanhf(cs * h.y + is * s1);
                    *(float2*)&out[OFF_SLOW + (size_t)b * 256 + nn] = o;
                }
            }
        }
    }
}

// ---------------------------------------------------------------------------
extern "C" void kernel_launch(void* const* d_in, const int* in_sizes, int n_in,
                              void* d_out, int out_size)
{
    const float* input       = (const float*)d_in[0];
    const float* io_h        = (const float*)d_in[1];
    const float* fast_h      = (const float*)d_in[2];
    const float* slow_h      = (const float*)d_in[3];
    const float* W_in_io     = (const float*)d_in[4];
    const float* b_in_io     = (const float*)d_in[5];
    const float* W_io_fast   = (const float*)d_in[6];
    const float* b_io_fast   = (const float*)d_in[7];
    const float* W_fast_fast = (const float*)d_in[8];
    const float* b_fast_fast = (const float*)d_in[9];
    const float* W_fast_slow = (const float*)d_in[10];
    const float* b_fast_slow = (const float*)d_in[11];
    const float* W_slow_slow = (const float*)d_in[12];
    const float* b_slow_slow = (const float*)d_in[13];
    const float* W_slow_fast = (const float*)d_in[14];
    const float* b_slow_fast = (const float*)d_in[15];
    const float* W_fast_io   = (const float*)d_in[16];
    const float* b_fast_io   = (const float*)d_in[17];
    const float* W_io_io     = (const float*)d_in[18];
    const float* b_io_io     = (const float*)d_in[19];
    const float* W_io_out    = (const float*)d_in[20];
    const float* b_io_out    = (const float*)d_in[21];

    cudaFuncSetAttribute(mtrnn_mma, cudaFuncAttributeMaxDynamicSharedMemorySize,
                         SM_TOTAL);

    prep<<<ABLKS + WBLKS + BBLKS, 256>>>(
        input, io_h, fast_h, slow_h,
        W_in_io, W_io_io, W_fast_io, W_io_fast, W_fast_fast,
        W_slow_fast, W_fast_slow, W_slow_slow, W_io_out,
        b_in_io, b_io_io, b_fast_io, b_io_fast, b_fast_fast,
        b_slow_fast, b_fast_slow, b_slow_slow, b_io_out);

    dim3 grid(NPAD / 128, BATCH / 128);
    mtrnn_mma<<<grid, 256, SM_TOTAL>>>(io_h, fast_h, slow_h, (float*)d_out);
}